// round 17
// baseline (speedup 1.0000x reference)
#include <cuda_runtime.h>
#include <cuda_bf16.h>
#include <cuda_fp16.h>
#include <math.h>
#include <stdint.h>

#define BATCH 4
#define SEQ   4096
#define CDIM  128
#define MTOT  (BATCH*SEQ)
#define KVT   64
#define NTILES (SEQ/KVT)    // 64

// fp16 operands: Q, K, V^T single fp16. V stored TRANSPOSED: [b][c][n].
// Q carries log2(e) folded into its scale (exp2 softmax).
__device__ __half g_Qh[MTOT*CDIM];
__device__ __half g_Kh[MTOT*CDIM];
__device__ __half g_Vth[MTOT*CDIM];

// ---------------- warp-MMA helpers (baseline PTX, sm_80+) ----------------
__device__ __forceinline__ uint32_t smem_u32(const void* p) {
    uint32_t a;
    asm("{ .reg .u64 t; cvta.to.shared.u64 t, %1; cvt.u32.u64 %0, t; }" : "=r"(a) : "l"(p));
    return a;
}
#define LDSM_X4(r0, r1, r2, r3, addr) \
    asm volatile("ldmatrix.sync.aligned.m8n8.x4.shared.b16 {%0,%1,%2,%3}, [%4];" \
        : "=r"(r0), "=r"(r1), "=r"(r2), "=r"(r3) : "r"(addr))

__device__ __forceinline__ void mma_fp16(float c[4], const uint32_t a[4],
                                         uint32_t b0, uint32_t b1) {
    asm("mma.sync.aligned.m16n8k16.row.col.f32.f16.f16.f32 "
        "{%0,%1,%2,%3}, {%4,%5,%6,%7}, {%8,%9}, {%0,%1,%2,%3};"
        : "+f"(c[0]), "+f"(c[1]), "+f"(c[2]), "+f"(c[3])
        : "r"(a[0]), "r"(a[1]), "r"(a[2]), "r"(a[3]), "r"(b0), "r"(b1));
}

#define CP_ASYNC16(dst_u32, src_ptr) \
    asm volatile("cp.async.cg.shared.global [%0], [%1], 16;" \
        :: "r"(dst_u32), "l"(src_ptr) : "memory")
#define CP_COMMIT() asm volatile("cp.async.commit_group;" ::: "memory")
#define CP_WAIT0()  asm volatile("cp.async.wait_group 0;" ::: "memory")

// fp16 helpers
__device__ __forceinline__ uint32_t packh_hi2(float a, float b, float& ra, float& rb) {
    __half2 h = __floats2half2_rn(a, b);
    ra = a - __half2float(__low2half(h));
    rb = b - __half2float(__high2half(h));
    return *(uint32_t*)&h;
}
__device__ __forceinline__ uint32_t packh2(float a, float b) {
    __half2 h = __floats2half2_rn(a, b);
    return *(uint32_t*)&h;
}

#define QSTR 136   // 16b-elem stride (272B): conflict-free ldmatrix

// ---------------------------------------------------------------------------
// Kernel 1: fused QKV projection via fp16 2-chain HMMA (X hi/lo limbs x W fp16),
// ONE WAVE (grid 128, 256 thr). W slices pipelined via cp.async.
// Q stored with log2(e)/(sqrt(C)*scale) folded in; K, V^T single fp16.
// (UNCHANGED from the validated 15.5us configuration.)
// ---------------------------------------------------------------------------
#define XH_OFF 0
#define XL_OFF 34816
#define WH_OFF 69632
#define WBUF_OFF 104448             // 128 x 128 fp32 dense = 65536 B
#define QKV_SMEM (WBUF_OFF + 65536) // 169984 B

__device__ __forceinline__ void qkv_prefetch_w(uint32_t sb, const float* Wfc,
                                               int cbase, int tid) {
    #pragma unroll
    for (int i = 0; i < 16; i++) {
        int idx = i * 256 + tid;               // 0..4095 float4
        int k = idx >> 5, n = (idx & 31) << 2;
        CP_ASYNC16(sb + WBUF_OFF + idx * 16, Wfc + k * 384 + cbase + n);
    }
    CP_COMMIT();
}

__global__ __launch_bounds__(256, 1)
void qkv_kernel(const float* __restrict__ x, const float* __restrict__ Wfc,
                const float* __restrict__ bfc, const float* __restrict__ scale) {
    extern __shared__ char sm[];
    const uint32_t sb = smem_u32(sm);
    const int tid = threadIdx.x, lane = tid & 31, w = tid >> 5;
    const int mbase = blockIdx.x * 128;

    const int bn  = (lane & 7) | ((lane & 16) >> 1);
    const int bk8 = (lane & 8);
    const int ar  = lane & 15;
    const int ac8 = (lane >> 4) << 3;

    __half* WH = (__half*)(sm + WH_OFF);
    const float* WB = (const float*)(sm + WBUF_OFF);

    qkv_prefetch_w(sb, Wfc, 0, tid);

    // ---- X tile -> fp16 hi/lo limbs in SMEM (ONCE) ----
    #pragma unroll
    for (int i = 0; i < 16; i++) {
        int idx = i * 256 + tid;
        int r = idx >> 5, c = (idx & 31) << 2;
        float4 v = *(const float4*)(x + (size_t)(mbase + r) * CDIM + c);
        float e0, e1;
        uint32_t h0 = packh_hi2(v.x, v.y, e0, e1);
        uint32_t l0 = packh2(e0, e1);
        uint32_t h1 = packh_hi2(v.z, v.w, e0, e1);
        uint32_t l1 = packh2(e0, e1);
        *(uint2*)(sm + XH_OFF + r * (QSTR * 2) + c * 2) = make_uint2(h0, h1);
        *(uint2*)(sm + XL_OFF + r * (QSTR * 2) + c * 2) = make_uint2(l0, l1);
    }
    __syncthreads();

    uint32_t xh[8][4], xl[8][4];
    #pragma unroll
    for (int kk = 0; kk < 8; kk++) {
        uint32_t a = sb + XH_OFF + ((w * 16 + ar) * QSTR + kk * 16 + ac8) * 2;
        LDSM_X4(xh[kk][0], xh[kk][1], xh[kk][2], xh[kk][3], a);
        uint32_t a2 = sb + XL_OFF + ((w * 16 + ar) * QSTR + kk * 16 + ac8) * 2;
        LDSM_X4(xl[kk][0], xl[kk][1], xl[kk][2], xl[kk][3], a2);
    }

    CP_WAIT0();
    __syncthreads();

    const int r0 = w * 16 + (lane >> 2);
    const int cb = (lane & 3) * 2;

    for (int sel = 0; sel < 3; sel++) {
        const int cbase = sel * 128;

        #pragma unroll
        for (int i = 0; i < 64; i++) {
            int idx = i * 256 + tid;
            int n = idx & 127, k = idx >> 7;
            WH[n * QSTR + k] = __float2half(WB[k * 128 + n]);
        }
        __syncthreads();

        if (sel < 2) qkv_prefetch_w(sb, Wfc, cbase + 128, tid);

        float co[16][4];
        #pragma unroll
        for (int i = 0; i < 16; i++)
            #pragma unroll
            for (int j = 0; j < 4; j++) co[i][j] = 0.f;

        {
            uint32_t cur[4], nxt[4];
            LDSM_X4(cur[0], cur[1], cur[2], cur[3],
                    sb + WH_OFF + (bn * (QSTR * 2)) + bk8 * 2);
            #pragma unroll
            for (int s = 0; s < 64; s++) {
                if (s < 63) {
                    int s1 = s + 1;
                    int kk1 = s1 >> 3, nbp1 = s1 & 7;
                    uint32_t off = ((nbp1 * 16 + bn) * (QSTR * 2)) + (kk1 * 16 + bk8) * 2;
                    LDSM_X4(nxt[0], nxt[1], nxt[2], nxt[3], sb + WH_OFF + off);
                }
                int kk = s >> 3, nbp = s & 7;
                mma_fp16(co[2 * nbp],     xh[kk], cur[0], cur[1]);
                mma_fp16(co[2 * nbp + 1], xh[kk], cur[2], cur[3]);
                mma_fp16(co[2 * nbp],     xl[kk], cur[0], cur[1]);
                mma_fp16(co[2 * nbp + 1], xl[kk], cur[2], cur[3]);
                cur[0] = nxt[0]; cur[1] = nxt[1]; cur[2] = nxt[2]; cur[3] = nxt[3];
            }
        }

        if (sel < 2) {
            const float mul = (sel == 0)
                ? (1.4426950408889634f / (sqrtf((float)CDIM) * scale[0])) : 1.0f;
            __half* dst = sel ? g_Kh : g_Qh;
            #pragma unroll
            for (int nb = 0; nb < 16; nb++) {
                int col = nb * 8 + cb;
                float bx = bfc[cbase + col], by = bfc[cbase + col + 1];
                uint32_t v01 = packh2((co[nb][0] + bx) * mul, (co[nb][1] + by) * mul);
                uint32_t v23 = packh2((co[nb][2] + bx) * mul, (co[nb][3] + by) * mul);
                *(uint32_t*)(dst + (size_t)(mbase + r0) * CDIM + col) = v01;
                *(uint32_t*)(dst + (size_t)(mbase + r0 + 8) * CDIM + col) = v23;
            }
            CP_WAIT0();
            __syncthreads();
        } else {
            float* T = (float*)sm;
            __syncthreads();
            #pragma unroll
            for (int nb = 0; nb < 16; nb++) {
                int col = nb * 8 + cb;
                float bx = bfc[cbase + col], by = bfc[cbase + col + 1];
                T[r0 * 132 + col]           = co[nb][0] + bx;
                T[r0 * 132 + col + 1]       = co[nb][1] + by;
                T[(r0 + 8) * 132 + col]     = co[nb][2] + bx;
                T[(r0 + 8) * 132 + col + 1] = co[nb][3] + by;
            }
            __syncthreads();
            const int c = tid & 127, seg = tid >> 7;
            const int bb = mbase >> 12;
            size_t basea = ((size_t)(bb * CDIM + c)) * SEQ + (mbase & 4095) + seg * 64;
            uint32_t hw[32];
            #pragma unroll
            for (int u = 0; u < 32; u++) {
                float v0 = T[(seg * 64 + 2 * u) * 132 + c];
                float v1 = T[(seg * 64 + 2 * u + 1) * 132 + c];
                hw[u] = packh2(v0, v1);
            }
            #pragma unroll
            for (int q = 0; q < 8; q++)
                *(uint4*)(g_Vth + basea + 8 * q) =
                    make_uint4(hw[4*q], hw[4*q+1], hw[4*q+2], hw[4*q+3]);
        }
    }
}

// ---------------------------------------------------------------------------
// Kernel 2: fp16 single-chain flash attention, 64-row Q tiles, KVT=64,
// 128 threads (4 warps), 2 CTAs/SM (grid 256 = one wave at occupancy 2).
// Cross-CTA overlap supplies the independent instruction streams that the
// lockstep single-CTA version lacked. exp2 softmax; cp.async double-buffered.
// ---------------------------------------------------------------------------
#define VSTR 72
#define OFF_KH 0                    // 64 x QSTR fp16 = 17408 B
#define OFF_VH 17408                // 128 x VSTR fp16 = 18432 B
#define BUFSZ  35840
#define SM_TOT (2*BUFSZ)            // 71680 per CTA; x2 CTAs = 143360 <= 228KB

__device__ __forceinline__ void prefetch_tile(uint32_t sbuf, int b, int kr0, int tid) {
    #pragma unroll
    for (int i = 0; i < 8; i++) {
        int idx = i * 128 + tid;               // 0..1023 uint4
        int r = idx >> 4, c = (idx & 15) << 3;
        size_t g = (size_t)(b * SEQ + kr0 + r) * CDIM + c;
        CP_ASYNC16(sbuf + OFF_KH + r * (QSTR * 2) + c * 2, g_Kh + g);
    }
    #pragma unroll
    for (int i = 0; i < 8; i++) {
        int idx = i * 128 + tid;               // 0..1023 uint4
        int r = idx >> 3, j8 = (idx & 7) << 3;
        size_t g = (size_t)(b * CDIM + r) * SEQ + kr0 + j8;
        CP_ASYNC16(sbuf + OFF_VH + r * (VSTR * 2) + j8 * 2, g_Vth + g);
    }
    CP_COMMIT();
}

// S for one 32-col quarter q (KV cols 32q..32q+31); register-pipelined.
__device__ __forceinline__ void s_quarter(float cs[4][4], const uint32_t qh[8][4],
                                          uint32_t skbase, int q, int bn, int bk8) {
    #pragma unroll
    for (int i = 0; i < 4; i++)
        #pragma unroll
        for (int j = 0; j < 4; j++) cs[i][j] = 0.f;
    uint32_t cur[4], nxt[4];
    LDSM_X4(cur[0], cur[1], cur[2], cur[3],
            skbase + (((2 * q) * 16 + bn) * (QSTR * 2)) + bk8 * 2);
    #pragma unroll
    for (int s = 0; s < 16; s++) {
        if (s < 15) {
            int s1 = s + 1;
            int kk1 = s1 >> 1, j1 = s1 & 1;
            uint32_t off = (((2 * q + j1) * 16 + bn) * (QSTR * 2)) + (kk1 * 16 + bk8) * 2;
            LDSM_X4(nxt[0], nxt[1], nxt[2], nxt[3], skbase + off);
        }
        int kk = s >> 1, j = s & 1;
        mma_fp16(cs[2 * j],     qh[kk], cur[0], cur[1]);
        mma_fp16(cs[2 * j + 1], qh[kk], cur[2], cur[3]);
        cur[0] = nxt[0]; cur[1] = nxt[1]; cur[2] = nxt[2]; cur[3] = nxt[3];
    }
}

// exp2 + l accumulation + pack quarter into pa0, pa1.
__device__ __forceinline__ void exp_pack_q(float cs[4][4], uint32_t* pa0, uint32_t* pa1,
                                           float& l0, float& l1) {
    #pragma unroll
    for (int nb = 0; nb < 4; nb++) {
        cs[nb][0] = exp2f(cs[nb][0]);
        cs[nb][1] = exp2f(cs[nb][1]);
        cs[nb][2] = exp2f(cs[nb][2]);
        cs[nb][3] = exp2f(cs[nb][3]);
        l0 += cs[nb][0] + cs[nb][1];
        l1 += cs[nb][2] + cs[nb][3];
    }
    pa0[0] = packh2(cs[0][0], cs[0][1]);
    pa0[1] = packh2(cs[0][2], cs[0][3]);
    pa0[2] = packh2(cs[1][0], cs[1][1]);
    pa0[3] = packh2(cs[1][2], cs[1][3]);
    pa1[0] = packh2(cs[2][0], cs[2][1]);
    pa1[1] = packh2(cs[2][2], cs[2][3]);
    pa1[2] = packh2(cs[3][0], cs[3][1]);
    pa1[3] = packh2(cs[3][2], cs[3][3]);
}

// PV for quarter q (kv rows 32q..32q+31), V in VSTR layout; register-pipelined.
__device__ __forceinline__ void pv_pair(float co[16][4], const uint32_t pa0[4],
                                        const uint32_t pa1[4],
                                        uint32_t svbase, int q, int bn, int bk8) {
    uint32_t cur[4], nxt[4];
    LDSM_X4(cur[0], cur[1], cur[2], cur[3],
            svbase + (bn * (VSTR * 2)) + ((2 * q) * 16 + bk8) * 2);
    #pragma unroll
    for (int s = 0; s < 16; s++) {
        if (s < 15) {
            int s1 = s + 1;
            int j1 = s1 >> 3, nbp1 = s1 & 7;
            uint32_t off = ((nbp1 * 16 + bn) * (VSTR * 2)) + (((2 * q + j1) * 16) + bk8) * 2;
            LDSM_X4(nxt[0], nxt[1], nxt[2], nxt[3], svbase + off);
        }
        int j = s >> 3, nbp = s & 7;
        const uint32_t* pa = j ? pa1 : pa0;
        mma_fp16(co[2 * nbp],     pa, cur[0], cur[1]);
        mma_fp16(co[2 * nbp + 1], pa, cur[2], cur[3]);
        cur[0] = nxt[0]; cur[1] = nxt[1]; cur[2] = nxt[2]; cur[3] = nxt[3];
    }
}

__global__ __launch_bounds__(128, 2)
void attn_kernel(const float* __restrict__ Wout, const float* __restrict__ bout,
                 float* __restrict__ out) {
    extern __shared__ char smem8[];
    const uint32_t sb = smem_u32(smem8);
    const int tid = threadIdx.x, lane = tid & 31, w = tid >> 5;
    const int b = blockIdx.y;
    const int qr0 = blockIdx.x * 64;

    const int bn  = (lane & 7) | ((lane & 16) >> 1);
    const int bk8 = (lane & 8);
    const int ar  = lane & 15;
    const int ac8 = (lane >> 4) << 3;

    prefetch_tile(sb, b, 0, tid);

    // ---- stage Q (64 rows, single fp16, log2e-scaled) via buffer-1 region ----
    uint32_t qh[8][4];
    {
        __half* Qs = (__half*)(smem8 + BUFSZ);
        const uint32_t qsb = sb + BUFSZ;
        #pragma unroll
        for (int i = 0; i < 8; i++) {
            int idx = i * 128 + tid;           // 0..1023 uint4 = 64x128 fp16
            int r = idx >> 4, c = (idx & 15) << 3;
            *(uint4*)(Qs + r * QSTR + c) =
                *(const uint4*)(g_Qh + (size_t)(b * SEQ + qr0 + r) * CDIM + c);
        }
        __syncthreads();
        #pragma unroll
        for (int kk = 0; kk < 8; kk++) {
            uint32_t a = qsb + ((w * 16 + ar) * QSTR + kk * 16 + ac8) * 2;
            LDSM_X4(qh[kk][0], qh[kk][1], qh[kk][2], qh[kk][3], a);
        }
    }

    float co[16][4];
    #pragma unroll
    for (int i = 0; i < 16; i++)
        #pragma unroll
        for (int j = 0; j < 4; j++) co[i][j] = 0.f;
    float l0 = 0.f, l1 = 0.f;

    CP_WAIT0();
    __syncthreads();

    for (int t = 0; t < NTILES; t++) {
        const uint32_t skbase = sb + (t & 1) * BUFSZ + OFF_KH;
        const uint32_t svbase = sb + (t & 1) * BUFSZ + OFF_VH;

        if (t + 1 < NTILES)
            prefetch_tile(sb + ((t + 1) & 1) * BUFSZ, b, (t + 1) * KVT, tid);

        uint32_t paA[2][4], paB[2][4];
        float cs[4][4];

        // pipeline: Sq0 ex0 Sq1 PV0 ex1 PV1
        s_quarter(cs, qh, skbase, 0, bn, bk8);
        exp_pack_q(cs, paA[0], paA[1], l0, l1);
        s_quarter(cs, qh, skbase, 1, bn, bk8);
        pv_pair(co, paA[0], paA[1], svbase, 0, bn, bk8);
        exp_pack_q(cs, paB[0], paB[1], l0, l1);
        pv_pair(co, paB[0], paB[1], svbase, 1, bn, bk8);

        CP_WAIT0();
        __syncthreads();
    }

    // ---- finalize l, normalize O ----
    l0 += __shfl_xor_sync(0xffffffffu, l0, 1);
    l0 += __shfl_xor_sync(0xffffffffu, l0, 2);
    l1 += __shfl_xor_sync(0xffffffffu, l1, 1);
    l1 += __shfl_xor_sync(0xffffffffu, l1, 2);
    const float inv0 = 1.0f / l0, inv1 = 1.0f / l1;
    #pragma unroll
    for (int nb = 0; nb < 16; nb++) {
        co[nb][0] *= inv0; co[nb][1] *= inv0;
        co[nb][2] *= inv1; co[nb][3] *= inv1;
    }

    // ---- W_out^T single fp16 -> SMEM (buffer 0 region, 34816 <= 35840) ----
    {
        __half* Wh = (__half*)smem8;
        for (int idx = tid; idx < CDIM * CDIM; idx += 128) {
            int cin = idx >> 7, cout = idx & 127;
            Wh[cout * QSTR + cin] = __float2half(Wout[idx]);
        }
    }

    // ---- O -> fp16 hi/lo A fragments ----
    uint32_t oah[8][4], oal[8][4];
    #pragma unroll
    for (int j = 0; j < 8; j++) {
        float e0, e1;
        oah[j][0] = packh_hi2(co[2*j][0],   co[2*j][1],   e0, e1); oal[j][0] = packh2(e0, e1);
        oah[j][1] = packh_hi2(co[2*j][2],   co[2*j][3],   e0, e1); oal[j][1] = packh2(e0, e1);
        oah[j][2] = packh_hi2(co[2*j+1][0], co[2*j+1][1], e0, e1); oal[j][2] = packh2(e0, e1);
        oah[j][3] = packh_hi2(co[2*j+1][2], co[2*j+1][3], e0, e1); oal[j][3] = packh2(e0, e1);
    }
    __syncthreads();

    // ---- D = O @ W_out (2 chains) ----
    #pragma unroll
    for (int i = 0; i < 16; i++)
        #pragma unroll
        for (int j = 0; j < 4; j++) co[i][j] = 0.f;

    #pragma unroll
    for (int kk = 0; kk < 8; kk++) {
        #pragma unroll
        for (int nbp = 0; nbp < 8; nbp++) {
            uint32_t off = ((nbp * 16 + bn) * (QSTR * 2)) + (kk * 16 + bk8) * 2;
            uint32_t h0, h1, h2, h3;
            LDSM_X4(h0, h1, h2, h3, sb + off);
            mma_fp16(co[2 * nbp],     oah[kk], h0, h1);
            mma_fp16(co[2 * nbp + 1], oah[kk], h2, h3);
            mma_fp16(co[2 * nbp],     oal[kk], h0, h1);
            mma_fp16(co[2 * nbp + 1], oal[kk], h2, h3);
        }
    }

    // ---- + bias, store ----
    {
        const int r0g = qr0 + w * 16 + (lane >> 2);
        const int cb = (lane & 3) * 2;
        float* base0 = out + (size_t)(b * SEQ + r0g) * CDIM;
        float* base1 = base0 + 8 * CDIM;
        #pragma unroll
        for (int nb = 0; nb < 16; nb++) {
            int col = nb * 8 + cb;
            float bx = bout[col], by = bout[col + 1];
            float2 v0 = make_float2(co[nb][0] + bx, co[nb][1] + by);
            float2 v1 = make_float2(co[nb][2] + bx, co[nb][3] + by);
            *(float2*)(base0 + col) = v0;
            *(float2*)(base1 + col) = v1;
        }
    }
}

// ---------------------------------------------------------------------------
extern "C" void kernel_launch(void* const* d_in, const int* in_sizes, int n_in,
                              void* d_out, int out_size) {
    const float* x    = (const float*)d_in[0];
    const float* Wfc  = (const float*)d_in[1];
    const float* bfc  = (const float*)d_in[2];
    const float* Wout = (const float*)d_in[3];
    const float* bo   = (const float*)d_in[4];
    const float* sc   = (const float*)d_in[5];
    float* out = (float*)d_out;

    cudaFuncSetAttribute(qkv_kernel, cudaFuncAttributeMaxDynamicSharedMemorySize, QKV_SMEM);
    cudaFuncSetAttribute(attn_kernel, cudaFuncAttributeMaxDynamicSharedMemorySize, SM_TOT);

    qkv_kernel<<<128, 256, QKV_SMEM>>>(x, Wfc, bfc, sc);
    attn_kernel<<<dim3(64, 4), 128, SM_TOT>>>(Wout, bo, out);
}